// round 16
// baseline (speedup 1.0000x reference)
#include <cuda_runtime.h>

#define NUM_CLS   8
#define MAX_INST  64
#define NB        32            // batch
#define HW        (1024*1024)   // pixels per sample
#define HT        128           // threads per block
#define CHUNKS    64            // blocks per sample along pixel dim
#define GRID      (NB * CHUNKS) // 2048 blocks ~= 2 waves at 7 blocks/SM

__device__ __align__(16) int g_inst_sizes[NB * MAX_INST];  // static-zero; reset each run
__device__ unsigned int g_done;                            // static-zero; reset each run

// Fused kernel: per-block 64-bin histogram, packed-u8 counters (word w=bin&15,
// byte bin>>4; bank = tid%32 -> conflict-free), replicated into FOUR separate
// __shared__ arrays (lane .x->A, .y->B, .z->C, .w->D). Distinct arrays cannot
// alias, so the 4 LDS of each quad issue in parallel -> the per-thread
// LDS->IADD->STS RAW chain (the R11/R14 cap) is broken 4-wide.
__global__ __launch_bounds__(HT, 7) void fused_kernel(const int*   __restrict__ mask,
                                                      const float* __restrict__ pred,
                                                      const int*   __restrict__ label_raw,
                                                      float*       __restrict__ out) {
    __shared__ __align__(16) unsigned int cntA[16 * HT];   // 8 KB each
    __shared__ __align__(16) unsigned int cntB[16 * HT];
    __shared__ __align__(16) unsigned int cntC[16 * HT];
    __shared__ __align__(16) unsigned int cntD[16 * HT];
    __shared__ int binsum[MAX_INST];
    __shared__ unsigned int s_ticket;

    const int tid = threadIdx.x;

    #pragma unroll
    for (int i = tid; i < 16 * HT; i += HT) {
        cntA[i] = 0u; cntB[i] = 0u; cntC[i] = 0u; cntD[i] = 0u;
    }
    if (tid < MAX_INST) binsum[tid] = 0;
    __syncthreads();

    const int sample = blockIdx.y;
    const int chunk  = blockIdx.x;
    const int elems  = HW / CHUNKS;     // 16384 per block -> 128 per thread

    const int4* __restrict__ p =
        (const int4*)(mask + (size_t)sample * HW + (size_t)chunk * elems) + tid;

    // One int4 -> 4 increments, one per replica: LDS x4 (independent arrays,
    // back-to-back issue), IADD x4, STS x4. Max 32 hits per u8 counter.
#define QUAD(v) {                                                              \
        unsigned int _x = (unsigned int)(v).x, _y = (unsigned int)(v).y,       \
                     _z = (unsigned int)(v).z, _w = (unsigned int)(v).w;       \
        unsigned int _ix = ((_x & 15u) << 7) + tid;                            \
        unsigned int _iy = ((_y & 15u) << 7) + tid;                            \
        unsigned int _iz = ((_z & 15u) << 7) + tid;                            \
        unsigned int _iw = ((_w & 15u) << 7) + tid;                            \
        unsigned int _lA = cntA[_ix], _lB = cntB[_iy],                         \
                     _lC = cntC[_iz], _lD = cntD[_iw];                         \
        cntA[_ix] = _lA + (1u << ((_x & 48u) >> 1));                           \
        cntB[_iy] = _lB + (1u << ((_y & 48u) >> 1));                           \
        cntC[_iz] = _lC + (1u << ((_z & 48u) >> 1));                           \
        cntD[_iw] = _lD + (1u << ((_w & 48u) >> 1));                           \
    }

    // 32 int4/thread = 16 pipelined iterations of batch-2 (prefetch keeps
    // 2-4 LDG.128 in flight per warp while the quad updates issue).
    int4 a = p[0 * HT];
    int4 b = p[1 * HT];
    p += 2 * HT;
    #pragma unroll 1
    for (int it = 0; it < 15; it++) {
        int4 a2 = p[0 * HT];
        int4 b2 = p[1 * HT];
        p += 2 * HT;
        QUAD(a); QUAD(b);
        a = a2; b = b2;
    }
    QUAD(a); QUAD(b);
#undef QUAD
    __syncthreads();

    // Reduce: for each replica, word column w (16 cols x 128 slots); 8 threads
    // per column (j = tid>>4), each sums 16 staggered slots -> conflict-free.
    // sA holds bins w (lo16) / w+32 (hi16); sB holds w+16 / w+48.
    // Max per 16-bit half: 16 slots x 4 reps x 255 = 16320 < 65536.
    {
        const int w = tid & 15;
        const int j = tid >> 4;
        unsigned int sA = 0, sB = 0;
        #pragma unroll
        for (int i = 0; i < 16; i++) {
            const int idx = (w << 7) + j * 16 + ((i + tid) & 15);
            unsigned int vA = cntA[idx], vB = cntB[idx],
                         vC = cntC[idx], vD = cntD[idx];
            sA += (vA & 0x00FF00FFu) + (vB & 0x00FF00FFu)
                + (vC & 0x00FF00FFu) + (vD & 0x00FF00FFu);
            sB += ((vA >> 8) & 0x00FF00FFu) + ((vB >> 8) & 0x00FF00FFu)
                + ((vC >> 8) & 0x00FF00FFu) + ((vD >> 8) & 0x00FF00FFu);
        }
        atomicAdd(&binsum[w],      (int)(sA & 0xFFFFu));
        atomicAdd(&binsum[w + 16], (int)(sB & 0xFFFFu));
        atomicAdd(&binsum[w + 32], (int)(sA >> 16));
        atomicAdd(&binsum[w + 48], (int)(sB >> 16));
    }
    __syncthreads();
    if (tid < MAX_INST)
        atomicAdd(&g_inst_sizes[sample * MAX_INST + tid], binsum[tid]);

    // ---- last-block-done handoff ----
    __threadfence();
    __syncthreads();
    if (tid == 0) s_ticket = atomicAdd(&g_done, 1u);
    __syncthreads();
    if (s_ticket != GRID - 1) return;

    // ================= last block: loss computation =================
    __threadfence();                       // acquire: see all blocks' bin atomics

    int*   isz   = (int*)cntA;             // [2048] totals (8 KB)
    int*   cnts  = (int*)cntB;             // [256] per-class pixel counts
    float* red   = (float*)cntC;           // [4] warp partials
    int*   flags = (int*)cntD;

    for (int i = tid; i < NB * MAX_INST / 4; i += HT)
        ((int4*)isz)[i] = ((const int4*)g_inst_sizes)[i];     // L2-hot, 8 KB
    if (tid == 0) flags[0] = 0;
    for (int i = tid; i < NB * NUM_CLS; i += HT) cnts[i] = 0;
    __syncthreads();

    // Reset globals for the next graph replay.
    for (int i = tid; i < NB * MAX_INST / 4; i += HT)
        ((int4*)g_inst_sizes)[i] = make_int4(0, 0, 0, 0);
    if (tid == 0) g_done = 0u;

    // int64-vs-int32 layout detection: values < 32, so little-endian int64
    // means every odd 32-bit word of the first 64 values is 0.
    if (tid < 64) {
        if (label_raw[2 * tid + 1] != 0) atomicOr(&flags[0], 1);
    }
    __syncthreads();

    const int is64 = !flags[0];
    for (int q = tid; q < NB * 64; q += HT) {
        int b = q >> 6;
        int id, lbl;
        if (is64) { id = label_raw[4 * q]; lbl = label_raw[4 * q + 2]; }
        else      { id = label_raw[2 * q]; lbl = label_raw[2 * q + 1]; }
        if (lbl > 0 && lbl <= NUM_CLS)
            atomicAdd(&cnts[b * NUM_CLS + lbl - 1], isz[b * MAX_INST + (id & (MAX_INST - 1))]);
    }
    __syncthreads();

    float term = 0.0f;
    for (int q = tid; q < NB * NUM_CLS; q += HT) {
        float x  = pred[q];
        float cl = fminf((float)cnts[q] * (1.0f / 100.0f), 1.0f);
        term += fmaxf(x, 0.0f) - x * cl + log1pf(expf(-fabsf(x)));
    }
    #pragma unroll
    for (int o = 16; o; o >>= 1) term += __shfl_down_sync(0xffffffffu, term, o);
    if ((tid & 31) == 0) red[tid >> 5] = term;
    __syncthreads();
    if (tid < 4) {
        float sr = red[tid];
        sr += __shfl_down_sync(0xFu, sr, 2);
        sr += __shfl_down_sync(0xFu, sr, 1);
        if (tid == 0) out[0] = sr * (1.0f / (float)(NB * NUM_CLS));
    }
}

// ---------------- launch ----------------
extern "C" void kernel_launch(void* const* d_in, const int* in_sizes, int n_in,
                              void* d_out, int out_size) {
    const float* pred  = (const float*)d_in[0];          // [32, 8] f32
    const int*   mask  = (const int*)d_in[1];            // [32, 1024, 1024] i32
    const int*   label = (const int*)d_in[2];            // [32, 64, 2] i32 or i64
    float*       out   = (float*)d_out;

    dim3 grid(CHUNKS, NB);
    fused_kernel<<<grid, HT>>>(mask, pred, label, out);
}

// round 17
// speedup vs baseline: 1.2387x; 1.2387x over previous
#include <cuda_runtime.h>

#define NUM_CLS   8
#define MAX_INST  64
#define NB        32            // batch
#define HW        (1024*1024)   // pixels per sample
#define HT        256           // threads per block
#define CHUNKS    32            // blocks per sample along pixel dim
#define GRID      (NB * CHUNKS) // 1024 blocks = one wave at 7 blocks/SM

__device__ __align__(16) int g_inst_sizes[NB * MAX_INST];  // static-zero; reset each run
__device__ unsigned int g_done;                            // static-zero; reset each run

// Fused kernel: per-block 64-bin histogram, packed-u8 counters (word w=bin&15,
// byte bin>>4; bank = tid%32 -> conflict-free), replicated into TWO separate
// __shared__ arrays (.x,.z -> A; .y,.w -> B). Distinct arrays cannot alias, so
// consecutive LDS issue back-to-back, halving the LDS->IADD->STS chain exposure
// — at R11's exact occupancy (HT=256, 32 KB, 7 blocks/SM).
__global__ __launch_bounds__(HT, 7) void fused_kernel(const int*   __restrict__ mask,
                                                      const float* __restrict__ pred,
                                                      const int*   __restrict__ label_raw,
                                                      float*       __restrict__ out) {
    __shared__ __align__(16) unsigned int cntA[16 * HT];   // 16 KB
    __shared__ __align__(16) unsigned int cntB[16 * HT];   // 16 KB
    __shared__ int binsum[MAX_INST];
    __shared__ unsigned int s_ticket;

    const int tid = threadIdx.x;

    #pragma unroll
    for (int i = tid; i < 16 * HT; i += HT) { cntA[i] = 0u; cntB[i] = 0u; }
    if (tid < MAX_INST) binsum[tid] = 0;
    __syncthreads();

    const int sample = blockIdx.y;
    const int chunk  = blockIdx.x;
    const int elems  = HW / CHUNKS;     // 32768 per block -> 128 per thread

    const int4* __restrict__ p =
        (const int4*)(mask + (size_t)sample * HW + (size_t)chunk * elems) + tid;

    // One int4 -> 2 updates in A (.x,.z) + 2 in B (.y,.w); per counter <= 64.
#define QUAD(v) {                                                              \
        unsigned int _x = (unsigned int)(v).x, _y = (unsigned int)(v).y,       \
                     _z = (unsigned int)(v).z, _w = (unsigned int)(v).w;       \
        unsigned int _ix = ((_x & 15u) << 8) + tid;                            \
        unsigned int _iy = ((_y & 15u) << 8) + tid;                            \
        unsigned int _lA0 = cntA[_ix], _lB0 = cntB[_iy];                       \
        cntA[_ix] = _lA0 + (1u << ((_x & 48u) >> 1));                          \
        cntB[_iy] = _lB0 + (1u << ((_y & 48u) >> 1));                          \
        unsigned int _iz = ((_z & 15u) << 8) + tid;                            \
        unsigned int _iw = ((_w & 15u) << 8) + tid;                            \
        unsigned int _lA1 = cntA[_iz], _lB1 = cntB[_iw];                       \
        cntA[_iz] = _lA1 + (1u << ((_z & 48u) >> 1));                          \
        cntB[_iw] = _lB1 + (1u << ((_w & 48u) >> 1));                          \
    }

    // 32 int4/thread = 16 pipelined iterations of batch-2.
    int4 a = p[0 * HT];
    int4 b = p[1 * HT];
    p += 2 * HT;
    #pragma unroll 1
    for (int it = 0; it < 15; it++) {
        int4 a2 = p[0 * HT];            // prefetch next batch BEFORE consuming
        int4 b2 = p[1 * HT];
        p += 2 * HT;
        QUAD(a); QUAD(b);
        a = a2; b = b2;
    }
    QUAD(a); QUAD(b);
#undef QUAD
    __syncthreads();

    // Reduce both replicas: word column w (16 cols x 256 slots); 16 threads
    // per column (j = tid>>4), each sums 16 staggered slots -> conflict-free.
    // sA holds bins w (lo16) / w+32 (hi16); sB holds w+16 / w+48.
    // Max per 16-bit half: 16 slots x 2 reps x 64 = 2048 < 65536.
    {
        const int w = tid & 15;
        const int j = tid >> 4;
        unsigned int sA = 0, sB = 0;
        #pragma unroll
        for (int i = 0; i < 16; i++) {
            const int idx = (w << 8) + j * 16 + ((i + tid) & 15);
            unsigned int vA = cntA[idx], vB = cntB[idx];
            sA += (vA & 0x00FF00FFu) + (vB & 0x00FF00FFu);
            sB += ((vA >> 8) & 0x00FF00FFu) + ((vB >> 8) & 0x00FF00FFu);
        }
        atomicAdd(&binsum[w],      (int)(sA & 0xFFFFu));
        atomicAdd(&binsum[w + 16], (int)(sB & 0xFFFFu));
        atomicAdd(&binsum[w + 32], (int)(sA >> 16));
        atomicAdd(&binsum[w + 48], (int)(sB >> 16));
    }
    __syncthreads();
    if (tid < MAX_INST)
        atomicAdd(&g_inst_sizes[sample * MAX_INST + tid], binsum[tid]);

    // ---- last-block-done handoff ----
    __threadfence();
    __syncthreads();
    if (tid == 0) s_ticket = atomicAdd(&g_done, 1u);
    __syncthreads();
    if (s_ticket != GRID - 1) return;

    // ================= last block: loss computation =================
    __threadfence();                       // acquire: see all blocks' bin atomics

    int*   isz   = (int*)cntA;             // [2048] totals (8 KB)
    int*   cnts  = (int*)cntB;             // [256] per-class pixel counts
    float* red   = (float*)cntB + 512;     // [8] warp partials
    int*   flags = (int*)cntB + 520;

    for (int i = tid; i < NB * MAX_INST / 4; i += HT)
        ((int4*)isz)[i] = ((const int4*)g_inst_sizes)[i];     // L2-hot, 8 KB
    if (tid == 0) flags[0] = 0;
    if (tid < NB * NUM_CLS) cnts[tid] = 0;
    __syncthreads();

    // Reset globals for the next graph replay.
    for (int i = tid; i < NB * MAX_INST / 4; i += HT)
        ((int4*)g_inst_sizes)[i] = make_int4(0, 0, 0, 0);
    if (tid == 0) g_done = 0u;

    // int64-vs-int32 layout detection: values < 32, so little-endian int64
    // means every odd 32-bit word of the first 64 values is 0.
    if (tid < 64) {
        if (label_raw[2 * tid + 1] != 0) atomicOr(&flags[0], 1);
    }
    __syncthreads();

    const int is64 = !flags[0];
    for (int q = tid; q < NB * 64; q += HT) {
        int b = q >> 6;
        int id, lbl;
        if (is64) { id = label_raw[4 * q]; lbl = label_raw[4 * q + 2]; }
        else      { id = label_raw[2 * q]; lbl = label_raw[2 * q + 1]; }
        if (lbl > 0 && lbl <= NUM_CLS)
            atomicAdd(&cnts[b * NUM_CLS + lbl - 1], isz[b * MAX_INST + (id & (MAX_INST - 1))]);
    }
    __syncthreads();

    float term = 0.0f;
    if (tid < NB * NUM_CLS) {
        float x  = pred[tid];
        float cl = fminf((float)cnts[tid] * (1.0f / 100.0f), 1.0f);
        term = fmaxf(x, 0.0f) - x * cl + log1pf(expf(-fabsf(x)));
    }
    #pragma unroll
    for (int o = 16; o; o >>= 1) term += __shfl_down_sync(0xffffffffu, term, o);
    if ((tid & 31) == 0) red[tid >> 5] = term;
    __syncthreads();
    if (tid < 8) {
        float sr = red[tid];
        #pragma unroll
        for (int o = 4; o; o >>= 1) sr += __shfl_down_sync(0xffu, sr, o);
        if (tid == 0) out[0] = sr * (1.0f / (float)(NB * NUM_CLS));
    }
}

// ---------------- launch ----------------
extern "C" void kernel_launch(void* const* d_in, const int* in_sizes, int n_in,
                              void* d_out, int out_size) {
    const float* pred  = (const float*)d_in[0];          // [32, 8] f32
    const int*   mask  = (const int*)d_in[1];            // [32, 1024, 1024] i32
    const int*   label = (const int*)d_in[2];            // [32, 64, 2] i32 or i64
    float*       out   = (float*)d_out;

    dim3 grid(CHUNKS, NB);
    fused_kernel<<<grid, HT>>>(mask, pred, label, out);
}